// round 16
// baseline (speedup 1.0000x reference)
#include <cuda_runtime.h>
#include <math.h>
#include <stdint.h>

#define B_   2
#define S_   2048
#define D_   2048
#define H_   16
#define KV_  8
#define DH_  128

// ---------------- persistent scratch ----------------
__device__ float  g_qkv [B_ * S_ * 4096];
__device__ float  g_q   [B_ * H_  * S_ * DH_];   // d-permuted, tf32, pre-scaled
__device__ float  g_k   [B_ * KV_ * S_ * DH_];   // d-permuted, tf32
__device__ float  g_vt  [B_ * KV_ * DH_ * S_];   // V TRANSPOSED [b,kv,d,s], tf32
__device__ float  g_attn[B_ * S_ * D_];          // d-permuted, tf32
__device__ float2 g_rope[S_ * 64];
__device__ float  g_hid [B_ * S_ * D_];
__device__ float  g_wq  [D_ * D_];
__device__ float  g_wk  [1024 * D_];
__device__ float  g_wv  [1024 * D_];
__device__ float  g_wo  [D_ * D_];

// ---------------- PTX helpers ----------------
__device__ __forceinline__ uint32_t smem_u32(const void* p) {
    uint32_t a;
    asm("{ .reg .u64 t; cvta.to.shared.u64 t, %1; cvt.u32.u64 %0, t; }" : "=r"(a) : "l"(p));
    return a;
}
__device__ __forceinline__ void cp_async16(uint32_t saddr, const void* gaddr) {
    asm volatile("cp.async.cg.shared.global [%0], [%1], 16;" :: "r"(saddr), "l"(gaddr));
}
__device__ __forceinline__ void cp_commit() {
    asm volatile("cp.async.commit_group;" ::: "memory");
}
template <int N>
__device__ __forceinline__ void cp_wait() {
    asm volatile("cp.async.wait_group %0;" :: "n"(N) : "memory");
}
__device__ __forceinline__ uint32_t f2tf32(float x) {
    uint32_t r;
    asm("cvt.rna.tf32.f32 %0, %1;" : "=r"(r) : "f"(x));
    return r;
}
__device__ __forceinline__ float rtf(float x) { return __uint_as_float(f2tf32(x)); }
__device__ __forceinline__ void mma_tf32(float* c, const uint32_t* a, const uint32_t* b) {
    asm volatile(
        "mma.sync.aligned.m16n8k8.row.col.f32.tf32.tf32.f32 "
        "{%0,%1,%2,%3}, {%4,%5,%6,%7}, {%8,%9}, {%0,%1,%2,%3};"
        : "+f"(c[0]), "+f"(c[1]), "+f"(c[2]), "+f"(c[3])
        : "r"(a[0]), "r"(a[1]), "r"(a[2]), "r"(a[3]), "r"(b[0]), "r"(b[1]));
}

// ---------------- prepass: tf32 round + k-permute, plus RoPE table ----------
__global__ __launch_bounds__(256) void permute_round_all(
    const float* s0, float* d0, int n0,
    const float* s1, float* d1, int n1,
    const float* s2, float* d2, int n2,
    const float* s3, float* d3, int n3,
    const float* s4, float* d4, int n4,
    float2* rope_tab)
{
    if (blockIdx.y == 5) {
        int idx = blockIdx.x * blockDim.x + threadIdx.x;
        if (idx >= S_ * 64) return;
        int s = idx >> 6, j = idx & 63;
        double inv = exp(-(double)j * (9.210340371976184 / 64.0));
        double ang = (double)s * inv;
        rope_tab[idx] = make_float2((float)cos(ang), (float)sin(ang));
        return;
    }
    const float* in; float* out; int ng;
    switch (blockIdx.y) {
        case 0: in = s0; out = d0; ng = n0; break;
        case 1: in = s1; out = d1; ng = n1; break;
        case 2: in = s2; out = d2; ng = n2; break;
        case 3: in = s3; out = d3; ng = n3; break;
        default: in = s4; out = d4; ng = n4; break;
    }
    int g = blockIdx.x * blockDim.x + threadIdx.x;
    if (g >= ng) return;
    float4 a = ((const float4*)in)[2 * g];
    float4 b = ((const float4*)in)[2 * g + 1];
    ((float4*)out)[2 * g]     = make_float4(rtf(a.x), rtf(b.x), rtf(a.y), rtf(b.y));
    ((float4*)out)[2 * g + 1] = make_float4(rtf(a.z), rtf(b.z), rtf(a.w), rtf(b.w));
}

// ---------------- mma.sync tf32 GEMM: 128x128 tile, 4 warps of 64x64, 4 stages
#define TM 128
#define TN 128
#define TK 16
#define KPAD 24
#define STAGE_FLOATS (2 * TM * KPAD)
#define STAGES 4
#define GEMM_SMEM (STAGES * STAGE_FLOATS * 4)

__global__ __launch_bounds__(128, 2) void gemm_mma(
    const float* __restrict__ A,
    const float* __restrict__ W0, const float* __restrict__ W1, const float* __restrict__ W2,
    float* __restrict__ C, int K, int ldc, int n1, int n2)
{
    extern __shared__ float smf[];
    const int tid  = threadIdx.x;
    const int wid  = tid >> 5, lane = tid & 31;
    const int qm   = lane >> 2, qk = lane & 3;
    const int m0   = blockIdx.y * TM;
    const int n0   = blockIdx.x * TN;
    const int wm   = (wid >> 1) * 64;
    const int wn   = (wid & 1) * 64;

    const float* W; int nr;
    if (n0 < n1)      { W = W0; nr = n0; }
    else if (n0 < n2) { W = W1; nr = n0 - n1; }
    else              { W = W2; nr = n0 - n2; }

    const float* Abase = A + (size_t)m0 * K;
    const float* Wbase = W + (size_t)nr * K;
    const uint32_t sb = smem_u32(smf);

    float acc[4][8][4];
    #pragma unroll
    for (int i = 0; i < 4; ++i)
        #pragma unroll
        for (int j = 0; j < 8; ++j)
            #pragma unroll
            for (int r = 0; r < 4; ++r) acc[i][j][r] = 0.f;

    const int NCH = K / TK;

    auto load_chunk = [&](int c, int buf) {
        const uint32_t abuf = sb + (uint32_t)buf * STAGE_FLOATS * 4;
        const uint32_t bbuf = abuf + TM * KPAD * 4;
        const int k0 = c * TK;
        #pragma unroll
        for (int i = 0; i < 4; ++i) {
            int idx = tid + i * 128;
            int row = idx >> 2, c4 = idx & 3;
            cp_async16(abuf + (uint32_t)(row * KPAD + c4 * 4) * 4,
                       Abase + (size_t)row * K + k0 + c4 * 4);
            cp_async16(bbuf + (uint32_t)(row * KPAD + c4 * 4) * 4,
                       Wbase + (size_t)row * K + k0 + c4 * 4);
        }
        cp_commit();
    };

    load_chunk(0, 0);
    load_chunk(1, 1);
    load_chunk(2, 2);

    for (int c = 0; c < NCH; ++c) {
        if (c + 3 <= NCH)      cp_wait<2>();
        else if (c + 2 == NCH) cp_wait<1>();
        else                   cp_wait<0>();
        __syncthreads();

        const int cn = c + STAGES - 1;
        if (cn < NCH) load_chunk(cn, cn & (STAGES - 1));

        const float* As = smf + (size_t)(c & (STAGES - 1)) * STAGE_FLOATS;
        const float* Bs = As + TM * KPAD;

        #pragma unroll
        for (int ks = 0; ks < 2; ++ks) {
            const int kc = ks * 8 + 2 * qk;
            uint32_t af[4][4], bf[8][2];
            #pragma unroll
            for (int mt = 0; mt < 4; ++mt) {
                float2 a0 = *(const float2*)(As + (wm + mt * 16 + qm)     * KPAD + kc);
                float2 a1 = *(const float2*)(As + (wm + mt * 16 + qm + 8) * KPAD + kc);
                af[mt][0] = __float_as_uint(a0.x);
                af[mt][1] = __float_as_uint(a1.x);
                af[mt][2] = __float_as_uint(a0.y);
                af[mt][3] = __float_as_uint(a1.y);
            }
            #pragma unroll
            for (int nt = 0; nt < 8; ++nt) {
                float2 bv = *(const float2*)(Bs + (wn + nt * 8 + qm) * KPAD + kc);
                bf[nt][0] = __float_as_uint(bv.x);
                bf[nt][1] = __float_as_uint(bv.y);
            }
            #pragma unroll
            for (int mt = 0; mt < 4; ++mt)
                #pragma unroll
                for (int nt = 0; nt < 8; ++nt)
                    mma_tf32(acc[mt][nt], af[mt], bf[nt]);
        }
    }

    #pragma unroll
    for (int mt = 0; mt < 4; ++mt) {
        const int r0 = m0 + wm + mt * 16 + qm;
        #pragma unroll
        for (int nt = 0; nt < 8; ++nt) {
            const int cc = n0 + wn + nt * 8 + 2 * qk;
            *(float2*)(C + (size_t)r0 * ldc + cc)       = make_float2(acc[mt][nt][0], acc[mt][nt][1]);
            *(float2*)(C + (size_t)(r0 + 8) * ldc + cc) = make_float2(acc[mt][nt][2], acc[mt][nt][3]);
        }
    }
}

// ---------------- canon conv + RMSNorm + RoPE + fused V^T, 4 seq/block ------
#define PP_SMEM (4 * 3072 * 4)

__global__ __launch_bounds__(256, 4) void postproc_kernel(
    const float* __restrict__ qkv,
    const float* __restrict__ cwq, const float* __restrict__ cwk, const float* __restrict__ cwv,
    const float* __restrict__ qnw, const float* __restrict__ knw,
    const float2* __restrict__ rope,
    float* __restrict__ qo, float* __restrict__ ko, float* __restrict__ vto)
{
    extern __shared__ float sm[];
    const int s0  = blockIdx.x * 4;
    const int b   = blockIdx.y;
    const int tid = threadIdx.x;
    const float* rowbase = qkv + ((size_t)b * S_ + s0) * 4096;
    const float sc = 0.08838834764831845f;

    #pragma unroll
    for (int it = 0; it < 3; ++it) {
        const int c4 = tid * 4 + it * 1024;
        const float* cw = (c4 < 2048) ? cwq + (size_t)c4 * 4
                                      : cwk + (size_t)(c4 - 2048) * 4;
        float4 w0 = *(const float4*)(cw);
        float4 w1 = *(const float4*)(cw + 4);
        float4 w2 = *(const float4*)(cw + 8);
        float4 w3 = *(const float4*)(cw + 12);

        float4 x[7];
        #pragma unroll
        for (int r = 0; r < 7; ++r) {
            int srow = s0 - 3 + r;
            x[r] = (srow >= 0)
                 ? *(const float4*)(rowbase + (ptrdiff_t)(r - 3) * 4096 + c4)
                 : make_float4(0.f, 0.f, 0.f, 0.f);
        }

        #pragma unroll
        for (int o = 0; o < 4; ++o) {
            float4 x0 = x[o + 3];
            float4 acc;
            acc.x = fmaf(w0.x, x0.x, x0.x);
            acc.y = fmaf(w1.x, x0.y, x0.y);
            acc.z = fmaf(w2.x, x0.z, x0.z);
            acc.w = fmaf(w3.x, x0.w, x0.w);
            acc.x = fmaf(w0.y, x[o + 2].x, acc.x);
            acc.y = fmaf(w1.y, x[o + 2].y, acc.y);
            acc.z = fmaf(w2.y, x[o + 2].z, acc.z);
            acc.w = fmaf(w3.y, x[o + 2].w, acc.w);
            acc.x = fmaf(w0.z, x[o + 1].x, acc.x);
            acc.y = fmaf(w1.z, x[o + 1].y, acc.y);
            acc.z = fmaf(w2.z, x[o + 1].z, acc.z);
            acc.w = fmaf(w3.z, x[o + 1].w, acc.w);
            acc.x = fmaf(w0.w, x[o].x, acc.x);
            acc.y = fmaf(w1.w, x[o].y, acc.y);
            acc.z = fmaf(w2.w, x[o].z, acc.z);
            acc.w = fmaf(w3.w, x[o].w, acc.w);
            *(float4*)(sm + o * 3072 + c4) = acc;
        }
    }

    {
        const int c4 = tid * 4 + 3072;
        const float* cw = cwv + (size_t)(c4 - 3072) * 4;
        float4 w0 = *(const float4*)(cw);
        float4 w1 = *(const float4*)(cw + 4);
        float4 w2 = *(const float4*)(cw + 8);
        float4 w3 = *(const float4*)(cw + 12);

        float4 x[7];
        #pragma unroll
        for (int r = 0; r < 7; ++r) {
            int srow = s0 - 3 + r;
            x[r] = (srow >= 0)
                 ? *(const float4*)(rowbase + (ptrdiff_t)(r - 3) * 4096 + c4)
                 : make_float4(0.f, 0.f, 0.f, 0.f);
        }

        float4 vacc[4];
        #pragma unroll
        for (int o = 0; o < 4; ++o) {
            float4 x0 = x[o + 3];
            float4 acc;
            acc.x = fmaf(w0.x, x0.x, x0.x);
            acc.y = fmaf(w1.x, x0.y, x0.y);
            acc.z = fmaf(w2.x, x0.z, x0.z);
            acc.w = fmaf(w3.x, x0.w, x0.w);
            acc.x = fmaf(w0.y, x[o + 2].x, acc.x);
            acc.y = fmaf(w1.y, x[o + 2].y, acc.y);
            acc.z = fmaf(w2.y, x[o + 2].z, acc.z);
            acc.w = fmaf(w3.y, x[o + 2].w, acc.w);
            acc.x = fmaf(w0.z, x[o + 1].x, acc.x);
            acc.y = fmaf(w1.z, x[o + 1].y, acc.y);
            acc.z = fmaf(w2.z, x[o + 1].z, acc.z);
            acc.w = fmaf(w3.z, x[o + 1].w, acc.w);
            acc.x = fmaf(w0.w, x[o].x, acc.x);
            acc.y = fmaf(w1.w, x[o].y, acc.y);
            acc.z = fmaf(w2.w, x[o].z, acc.z);
            acc.w = fmaf(w3.w, x[o].w, acc.w);
            vacc[o] = acc;
        }

        const int vch = c4 - 3072;
        const int kvh = vch >> 7;
        const int d   = vch & 127;
        float* vbase = vto + (((size_t)b * KV_ + kvh) * DH_ + d) * S_ + s0;
        *(float4*)(vbase)           = make_float4(rtf(vacc[0].x), rtf(vacc[1].x), rtf(vacc[2].x), rtf(vacc[3].x));
        *(float4*)(vbase + S_)      = make_float4(rtf(vacc[0].y), rtf(vacc[1].y), rtf(vacc[2].y), rtf(vacc[3].y));
        *(float4*)(vbase + 2 * S_)  = make_float4(rtf(vacc[0].z), rtf(vacc[1].z), rtf(vacc[2].z), rtf(vacc[3].z));
        *(float4*)(vbase + 3 * S_)  = make_float4(rtf(vacc[0].w), rtf(vacc[1].w), rtf(vacc[2].w), rtf(vacc[3].w));
    }
    __syncthreads();

    const int warp = tid >> 5, lane = tid & 31;
    const int j  = lane & 7;
    const int pj = (j < 4) ? 2 * j : 2 * j - 7;
    const int p0 = (lane & ~7) + pj;

    for (int t = warp; t < 96; t += 8) {
        const int o   = t / 24;
        const int h24 = t % 24;
        const int s   = s0 + o;
        const float2 cs0 = rope[(size_t)s * 64 + lane];
        const float2 cs1 = rope[(size_t)s * 64 + lane + 32];
        const bool isq  = h24 < 16;
        const int  base = o * 3072 + (isq ? h24 * 128 : 2048 + (h24 - 16) * 128);
        float v0 = sm[base + lane];
        float v1 = sm[base + lane + 32];
        float v2 = sm[base + lane + 64];
        float v3 = sm[base + lane + 96];
        float ss = v0*v0 + v1*v1 + v2*v2 + v3*v3;
        #pragma unroll
        for (int of = 16; of > 0; of >>= 1) ss += __shfl_xor_sync(0xffffffffu, ss, of);
        float r = rsqrtf(ss * (1.0f / 128.0f) + 1e-6f);
        const float* nw = isq ? qnw : knw;
        float a0 = v0 * r * nw[lane];
        float a1 = v1 * r * nw[lane + 32];
        float a2 = v2 * r * nw[lane + 64];
        float a3 = v3 * r * nw[lane + 96];
        float o_lo0 = a0 * cs0.x - a2 * cs0.y;
        float o_hi0 = a2 * cs0.x + a0 * cs0.y;
        float o_lo1 = a1 * cs1.x - a3 * cs1.y;
        float o_hi1 = a3 * cs1.x + a1 * cs1.y;
        float* dst;
        float f = 1.0f;
        if (isq) { dst = qo + (((size_t)b * H_  + h24)        * S_ + s) * DH_; f = sc; }
        else     { dst = ko + (((size_t)b * KV_ + (h24 - 16)) * S_ + s) * DH_; }
        dst[p0]      = rtf(o_lo0 * f);
        dst[p0 + 32] = rtf(o_lo1 * f);
        dst[p0 + 64] = rtf(o_hi0 * f);
        dst[p0 + 96] = rtf(o_hi1 * f);
    }
}

// ---------------- causal flash attention, tf32 mma.sync ----------------------
// Deferred-PV pipeline: ring slot j holds {K(j), V(j-1)}; iteration j does
// S(j); PV(j-1); exp(j).  exp MUFU overlaps the next iteration's S mmas.
#define FA_KS 136
#define FA_VS 72
#define FA_KTILE (64 * FA_KS)
#define FA_VTILE (128 * FA_VS)
#define FA_BUF  (FA_KTILE + FA_VTILE)
#define FA_SMEM (3 * FA_BUF * 4)
#define EP_S 132

__global__ __launch_bounds__(256) void flash_mma_kernel(
    const float* __restrict__ Q, const float* __restrict__ Kg,
    const float* __restrict__ Vg, float* __restrict__ O)
{
    extern __shared__ float fs[];

    const int qblk = gridDim.x - 1 - blockIdx.x;
    const int q0   = qblk * 128;
    const int h    = blockIdx.y;
    const int b    = blockIdx.z;
    const int tid  = threadIdx.x;
    const int w    = tid >> 5, lane = tid & 31;
    const int qm   = lane >> 2, qk = lane & 3;
    const int wrow = w * 16;

    const float* Qb = Q  + (((size_t)b * H_  + h)        * S_ + q0 + wrow) * DH_;
    const float* Kb = Kg + (((size_t)b * KV_ + (h >> 1)) * S_) * DH_;
    const float* Vb = Vg + (((size_t)b * KV_ + (h >> 1)) * DH_) * S_;   // V^T

    uint32_t qf[16][4];
    #pragma unroll
    for (int ks = 0; ks < 16; ++ks) {
        float2 q0v = *(const float2*)(Qb + (size_t)qm * DH_ + ks * 8 + 2 * qk);
        float2 q1v = *(const float2*)(Qb + (size_t)(qm + 8) * DH_ + ks * 8 + 2 * qk);
        qf[ks][0] = __float_as_uint(q0v.x);
        qf[ks][1] = __float_as_uint(q1v.x);
        qf[ks][2] = __float_as_uint(q0v.y);
        qf[ks][3] = __float_as_uint(q1v.y);
    }

    float o[16][4];
    #pragma unroll
    for (int nt = 0; nt < 16; ++nt)
        o[nt][0] = o[nt][1] = o[nt][2] = o[nt][3] = 0.f;
    float l0 = 0.f, l1 = 0.f;

    const int nb = 2 * (qblk + 1);
    const uint32_t fs_u = smem_u32(fs);

    // ring slot j: K(j) (if j<nb) and V(j-1) (if j>=1)
    auto prefetchKV = [&](int jidx) {
        const int buf = jidx % 3;
        const uint32_t kbuf = fs_u + (uint32_t)buf * FA_BUF * 4;
        const uint32_t vbuf = kbuf + FA_KTILE * 4;
        if (jidx < nb) {
            const int j0 = jidx * 64;
            #pragma unroll
            for (int i = 0; i < 8; ++i) {
                int idx = tid + i * 256;
                int row = idx >> 5, c4 = idx & 31;
                cp_async16(kbuf + (uint32_t)(row * FA_KS + c4 * 4) * 4,
                           Kb + (size_t)(j0 + row) * DH_ + c4 * 4);
            }
        }
        if (jidx >= 1) {
            const int jv0 = (jidx - 1) * 64;
            #pragma unroll
            for (int i = 0; i < 8; ++i) {
                int idx = tid + i * 256;
                int row = idx >> 4, c4 = idx & 15;
                cp_async16(vbuf + (uint32_t)(row * FA_VS + c4 * 4) * 4,
                           Vb + (size_t)row * S_ + jv0 + c4 * 4);
            }
        }
        cp_commit();
    };

    prefetchKV(0);    // group 0: K(0)
    prefetchKV(1);    // group 1: K(1) + V(0)

    uint32_t aP[8][4];

    for (int jb = 0; jb < nb; ++jb) {
        cp_wait<1>();             // group jb complete (K(jb), V(jb-1))
        __syncthreads();
        if (jb + 2 <= nb) prefetchKV(jb + 2);

        const int buf = jb % 3;
        const float* Kt = fs + (size_t)buf * FA_BUF;

        // ---- S(jb) ----
        float sv[8][4];
        #pragma unroll
        for (int nt = 0; nt < 8; ++nt) {
            sv[nt][0] = sv[nt][1] = sv[nt][2] = sv[nt][3] = 0.f;
            const float* kp = Kt + (nt * 8 + qm) * FA_KS + 2 * qk;
            #pragma unroll
            for (int ks = 0; ks < 16; ++ks) {
                float2 kv = *(const float2*)(kp + ks * 8);
                uint32_t bfr[2];
                bfr[0] = __float_as_uint(kv.x);
                bfr[1] = __float_as_uint(kv.y);
                mma_tf32(sv[nt], qf[ks], bfr);
            }
        }

        if (jb >= nb - 2) {
            const int j0 = jb * 64;
            const int r0 = q0 + wrow + qm, r1 = r0 + 8;
            #pragma unroll
            for (int nt = 0; nt < 8; ++nt) {
                const int c0 = j0 + nt * 8 + 2 * qk;
                if (c0     > r0) sv[nt][0] = -1e30f;
                if (c0 + 1 > r0) sv[nt][1] = -1e30f;
                if (c0     > r1) sv[nt][2] = -1e30f;
                if (c0 + 1 > r1) sv[nt][3] = -1e30f;
            }
        }

        // ---- PV(jb-1) with aP from previous iteration ----
        if (jb > 0) {
            const float* Vt = Kt + FA_KTILE;     // V(jb-1) lives in slot jb
            #pragma unroll
            for (int nt = 0; nt < 16; ++nt) {
                const float* vp = Vt + (nt * 8 + qm) * FA_VS + 2 * qk;
                #pragma unroll
                for (int ks = 0; ks < 8; ++ks) {
                    float2 vv = *(const float2*)(vp + ks * 8);
                    uint32_t bfr[2];
                    bfr[0] = __float_as_uint(vv.x);
                    bfr[1] = __float_as_uint(vv.y);
                    mma_tf32(o[nt], aP[ks], bfr);
                }
            }
        }

        // ---- exp(jb) -> aP (MUFU overlaps next iteration's S mmas) ----
        float rs0 = 0.f, rs1 = 0.f;
        #pragma unroll
        for (int nt = 0; nt < 8; ++nt) {
            float p00 = __expf(sv[nt][0]);
            float p01 = __expf(sv[nt][1]);
            float p10 = __expf(sv[nt][2]);
            float p11 = __expf(sv[nt][3]);
            rs0 += p00 + p01;
            rs1 += p10 + p11;
            aP[nt][0] = f2tf32(p00);
            aP[nt][1] = f2tf32(p10);
            aP[nt][2] = f2tf32(p01);
            aP[nt][3] = f2tf32(p11);
        }
        l0 += rs0;
        l1 += rs1;
    }

    // ---- final PV(nb-1): V(nb-1) lives in slot nb ----
    cp_wait<0>();
    __syncthreads();
    {
        const float* Vt = fs + (size_t)(nb % 3) * FA_BUF + FA_KTILE;
        #pragma unroll
        for (int nt = 0; nt < 16; ++nt) {
            const float* vp = Vt + (nt * 8 + qm) * FA_VS + 2 * qk;
            #pragma unroll
            for (int ks = 0; ks < 8; ++ks) {
                float2 vv = *(const float2*)(vp + ks * 8);
                uint32_t bfr[2];
                bfr[0] = __float_as_uint(vv.x);
                bfr[1] = __float_as_uint(vv.y);
                mma_tf32(o[nt], aP[ks], bfr);
            }
        }
    }

    // ---- l reduction ----
    l0 += __shfl_xor_sync(0xffffffffu, l0, 1);
    l0 += __shfl_xor_sync(0xffffffffu, l0, 2);
    l1 += __shfl_xor_sync(0xffffffffu, l1, 1);
    l1 += __shfl_xor_sync(0xffffffffu, l1, 2);
    const float il0 = 1.f / l0, il1 = 1.f / l1;

    // ---- epilogue: stage via smem, coalesced float4 writes ----
    __syncthreads();
    const int pos0 = (qk < 2) ? 4 * qk : 4 * qk - 7;
    const int pos1 = pos0 + 2;
    float* st0 = fs + (wrow + qm) * EP_S;
    float* st1 = st0 + 8 * EP_S;
    #pragma unroll
    for (int nt = 0; nt < 16; ++nt) {
        st0[nt * 8 + pos0] = o[nt][0] * il0;
        st0[nt * 8 + pos1] = o[nt][1] * il0;
        st1[nt * 8 + pos0] = o[nt][2] * il1;
        st1[nt * 8 + pos1] = o[nt][3] * il1;
    }
    __syncthreads();
    #pragma unroll
    for (int i = 0; i < 16; ++i) {
        int idx = tid + i * 256;
        int r = idx >> 5, c4 = (idx & 31) * 4;
        const float* src = fs + r * EP_S + c4;
        float4 v = make_float4(rtf(src[0]), rtf(src[1]), rtf(src[2]), rtf(src[3]));
        *(float4*)(O + ((size_t)b * S_ + q0 + r) * D_ + h * DH_ + c4) = v;
    }
}

// ---------------- launch ----------------
extern "C" void kernel_launch(void* const* d_in, const int* in_sizes, int n_in,
                              void* d_out, int out_size)
{
    const float* hidden = (const float*)d_in[0];
    const float* Wq     = (const float*)d_in[1];
    const float* Wk     = (const float*)d_in[2];
    const float* Wv     = (const float*)d_in[3];
    const float* Wo     = (const float*)d_in[4];
    const float* cwq    = (const float*)d_in[5];
    const float* cwk    = (const float*)d_in[6];
    const float* cwv    = (const float*)d_in[7];
    const float* qnw    = (const float*)d_in[8];
    const float* knw    = (const float*)d_in[9];
    float* out = (float*)d_out;

    float *qkv, *q, *k, *vt, *attn, *hid, *wq, *wk, *wv, *wo;
    float2* rope;
    cudaGetSymbolAddress((void**)&qkv,  g_qkv);
    cudaGetSymbolAddress((void**)&q,    g_q);
    cudaGetSymbolAddress((void**)&k,    g_k);
    cudaGetSymbolAddress((void**)&vt,   g_vt);
    cudaGetSymbolAddress((void**)&attn, g_attn);
    cudaGetSymbolAddress((void**)&rope, g_rope);
    cudaGetSymbolAddress((void**)&hid,  g_hid);
    cudaGetSymbolAddress((void**)&wq,   g_wq);
    cudaGetSymbolAddress((void**)&wk,   g_wk);
    cudaGetSymbolAddress((void**)&wv,   g_wv);
    cudaGetSymbolAddress((void**)&wo,   g_wo);

    const int nh = B_ * S_ * D_ / 8;
    const int nq = D_ * D_ / 8;
    const int nk = 1024 * D_ / 8;
    permute_round_all<<<dim3((nh + 255) / 256, 6), 256>>>(
        hidden, hid, nh,
        Wq, wq, nq,
        Wk, wk, nk,
        Wv, wv, nk,
        Wo, wo, nq,
        rope);

    cudaFuncSetAttribute(gemm_mma, cudaFuncAttributeMaxDynamicSharedMemorySize, GEMM_SMEM);

    gemm_mma<<<dim3(4096 / TN, (B_ * S_) / TM), 128, GEMM_SMEM>>>(
        hid, wq, wk, wv, qkv, 2048, 4096, 2048, 3072);

    cudaFuncSetAttribute(postproc_kernel, cudaFuncAttributeMaxDynamicSharedMemorySize, PP_SMEM);
    postproc_kernel<<<dim3(S_ / 4, B_), 256, PP_SMEM>>>(
        qkv, cwq, cwk, cwv, qnw, knw, rope, q, k, vt);

    cudaFuncSetAttribute(flash_mma_kernel, cudaFuncAttributeMaxDynamicSharedMemorySize, FA_SMEM);
    flash_mma_kernel<<<dim3(S_ / 128, H_, B_), 256, FA_SMEM>>>(q, k, vt, attn);

    gemm_mma<<<dim3(D_ / TN, (B_ * S_) / TM), 128, GEMM_SMEM>>>(
        attn, wo, wo, wo, out, 2048, 2048, 1 << 30, 1 << 30);
}

// round 17
// speedup vs baseline: 1.0227x; 1.0227x over previous
#include <cuda_runtime.h>
#include <math.h>
#include <stdint.h>

#define B_   2
#define S_   2048
#define D_   2048
#define H_   16
#define KV_  8
#define DH_  128

// ---------------- persistent scratch ----------------
__device__ float  g_qkv [B_ * S_ * 4096];
__device__ float  g_q   [B_ * H_  * S_ * DH_];   // d-permuted, tf32, pre-scaled
__device__ float  g_k   [B_ * KV_ * S_ * DH_];   // d-permuted, tf32
__device__ float  g_vt  [B_ * KV_ * DH_ * S_];   // V TRANSPOSED [b,kv,d,s], tf32
__device__ float  g_attn[B_ * S_ * D_];          // d-permuted, tf32
__device__ float2 g_rope[S_ * 64];
__device__ float  g_hid [B_ * S_ * D_];
__device__ float  g_wq  [D_ * D_];
__device__ float  g_wk  [1024 * D_];
__device__ float  g_wv  [1024 * D_];
__device__ float  g_wo  [D_ * D_];

// ---------------- PTX helpers ----------------
__device__ __forceinline__ uint32_t smem_u32(const void* p) {
    uint32_t a;
    asm("{ .reg .u64 t; cvta.to.shared.u64 t, %1; cvt.u32.u64 %0, t; }" : "=r"(a) : "l"(p));
    return a;
}
__device__ __forceinline__ void cp_async16(uint32_t saddr, const void* gaddr) {
    asm volatile("cp.async.cg.shared.global [%0], [%1], 16;" :: "r"(saddr), "l"(gaddr));
}
__device__ __forceinline__ void cp_commit() {
    asm volatile("cp.async.commit_group;" ::: "memory");
}
template <int N>
__device__ __forceinline__ void cp_wait() {
    asm volatile("cp.async.wait_group %0;" :: "n"(N) : "memory");
}
__device__ __forceinline__ uint32_t f2tf32(float x) {
    uint32_t r;
    asm("cvt.rna.tf32.f32 %0, %1;" : "=r"(r) : "f"(x));
    return r;
}
__device__ __forceinline__ float rtf(float x) { return __uint_as_float(f2tf32(x)); }
__device__ __forceinline__ void mma_tf32(float* c, const uint32_t* a, const uint32_t* b) {
    asm volatile(
        "mma.sync.aligned.m16n8k8.row.col.f32.tf32.tf32.f32 "
        "{%0,%1,%2,%3}, {%4,%5,%6,%7}, {%8,%9}, {%0,%1,%2,%3};"
        : "+f"(c[0]), "+f"(c[1]), "+f"(c[2]), "+f"(c[3])
        : "r"(a[0]), "r"(a[1]), "r"(a[2]), "r"(a[3]), "r"(b[0]), "r"(b[1]));
}

// ---------------- prepass: tf32 round + k-permute, plus RoPE table ----------
__global__ __launch_bounds__(256) void permute_round_all(
    const float* s0, float* d0, int n0,
    const float* s1, float* d1, int n1,
    const float* s2, float* d2, int n2,
    const float* s3, float* d3, int n3,
    const float* s4, float* d4, int n4,
    float2* rope_tab)
{
    if (blockIdx.y == 5) {
        int idx = blockIdx.x * blockDim.x + threadIdx.x;
        if (idx >= S_ * 64) return;
        int s = idx >> 6, j = idx & 63;
        double inv = exp(-(double)j * (9.210340371976184 / 64.0));
        double ang = (double)s * inv;
        rope_tab[idx] = make_float2((float)cos(ang), (float)sin(ang));
        return;
    }
    const float* in; float* out; int ng;
    switch (blockIdx.y) {
        case 0: in = s0; out = d0; ng = n0; break;
        case 1: in = s1; out = d1; ng = n1; break;
        case 2: in = s2; out = d2; ng = n2; break;
        case 3: in = s3; out = d3; ng = n3; break;
        default: in = s4; out = d4; ng = n4; break;
    }
    int g = blockIdx.x * blockDim.x + threadIdx.x;
    if (g >= ng) return;
    float4 a = ((const float4*)in)[2 * g];
    float4 b = ((const float4*)in)[2 * g + 1];
    ((float4*)out)[2 * g]     = make_float4(rtf(a.x), rtf(b.x), rtf(a.y), rtf(b.y));
    ((float4*)out)[2 * g + 1] = make_float4(rtf(a.z), rtf(b.z), rtf(a.w), rtf(b.w));
}

// ---------------- mma.sync tf32 GEMM: 128x128 tile, 4 warps of 64x64, 4 stages
#define TM 128
#define TN 128
#define TK 16
#define KPAD 24
#define STAGE_FLOATS (2 * TM * KPAD)
#define STAGES 4
#define GEMM_SMEM (STAGES * STAGE_FLOATS * 4)

__global__ __launch_bounds__(128, 2) void gemm_mma(
    const float* __restrict__ A,
    const float* __restrict__ W0, const float* __restrict__ W1, const float* __restrict__ W2,
    float* __restrict__ C, int K, int ldc, int n1, int n2)
{
    extern __shared__ float smf[];
    const int tid  = threadIdx.x;
    const int wid  = tid >> 5, lane = tid & 31;
    const int qm   = lane >> 2, qk = lane & 3;
    const int m0   = blockIdx.y * TM;
    const int n0   = blockIdx.x * TN;
    const int wm   = (wid >> 1) * 64;
    const int wn   = (wid & 1) * 64;

    const float* W; int nr;
    if (n0 < n1)      { W = W0; nr = n0; }
    else if (n0 < n2) { W = W1; nr = n0 - n1; }
    else              { W = W2; nr = n0 - n2; }

    const float* Abase = A + (size_t)m0 * K;
    const float* Wbase = W + (size_t)nr * K;
    const uint32_t sb = smem_u32(smf);

    float acc[4][8][4];
    #pragma unroll
    for (int i = 0; i < 4; ++i)
        #pragma unroll
        for (int j = 0; j < 8; ++j)
            #pragma unroll
            for (int r = 0; r < 4; ++r) acc[i][j][r] = 0.f;

    const int NCH = K / TK;

    auto load_chunk = [&](int c, int buf) {
        const uint32_t abuf = sb + (uint32_t)buf * STAGE_FLOATS * 4;
        const uint32_t bbuf = abuf + TM * KPAD * 4;
        const int k0 = c * TK;
        #pragma unroll
        for (int i = 0; i < 4; ++i) {
            int idx = tid + i * 128;
            int row = idx >> 2, c4 = idx & 3;
            cp_async16(abuf + (uint32_t)(row * KPAD + c4 * 4) * 4,
                       Abase + (size_t)row * K + k0 + c4 * 4);
            cp_async16(bbuf + (uint32_t)(row * KPAD + c4 * 4) * 4,
                       Wbase + (size_t)row * K + k0 + c4 * 4);
        }
        cp_commit();
    };

    load_chunk(0, 0);
    load_chunk(1, 1);
    load_chunk(2, 2);

    for (int c = 0; c < NCH; ++c) {
        if (c + 3 <= NCH)      cp_wait<2>();
        else if (c + 2 == NCH) cp_wait<1>();
        else                   cp_wait<0>();
        __syncthreads();

        const int cn = c + STAGES - 1;
        if (cn < NCH) load_chunk(cn, cn & (STAGES - 1));

        const float* As = smf + (size_t)(c & (STAGES - 1)) * STAGE_FLOATS;
        const float* Bs = As + TM * KPAD;

        #pragma unroll
        for (int ks = 0; ks < 2; ++ks) {
            const int kc = ks * 8 + 2 * qk;
            uint32_t af[4][4], bf[8][2];
            #pragma unroll
            for (int mt = 0; mt < 4; ++mt) {
                float2 a0 = *(const float2*)(As + (wm + mt * 16 + qm)     * KPAD + kc);
                float2 a1 = *(const float2*)(As + (wm + mt * 16 + qm + 8) * KPAD + kc);
                af[mt][0] = __float_as_uint(a0.x);
                af[mt][1] = __float_as_uint(a1.x);
                af[mt][2] = __float_as_uint(a0.y);
                af[mt][3] = __float_as_uint(a1.y);
            }
            #pragma unroll
            for (int nt = 0; nt < 8; ++nt) {
                float2 bv = *(const float2*)(Bs + (wn + nt * 8 + qm) * KPAD + kc);
                bf[nt][0] = __float_as_uint(bv.x);
                bf[nt][1] = __float_as_uint(bv.y);
            }
            #pragma unroll
            for (int mt = 0; mt < 4; ++mt)
                #pragma unroll
                for (int nt = 0; nt < 8; ++nt)
                    mma_tf32(acc[mt][nt], af[mt], bf[nt]);
        }
    }

    #pragma unroll
    for (int mt = 0; mt < 4; ++mt) {
        const int r0 = m0 + wm + mt * 16 + qm;
        #pragma unroll
        for (int nt = 0; nt < 8; ++nt) {
            const int cc = n0 + wn + nt * 8 + 2 * qk;
            *(float2*)(C + (size_t)r0 * ldc + cc)       = make_float2(acc[mt][nt][0], acc[mt][nt][1]);
            *(float2*)(C + (size_t)(r0 + 8) * ldc + cc) = make_float2(acc[mt][nt][2], acc[mt][nt][3]);
        }
    }
}

// ---------------- canon conv + RMSNorm + RoPE + fused V^T, 4 seq/block ------
#define PP_SMEM (4 * 3072 * 4)

__global__ __launch_bounds__(256, 4) void postproc_kernel(
    const float* __restrict__ qkv,
    const float* __restrict__ cwq, const float* __restrict__ cwk, const float* __restrict__ cwv,
    const float* __restrict__ qnw, const float* __restrict__ knw,
    const float2* __restrict__ rope,
    float* __restrict__ qo, float* __restrict__ ko, float* __restrict__ vto)
{
    extern __shared__ float sm[];
    const int s0  = blockIdx.x * 4;
    const int b   = blockIdx.y;
    const int tid = threadIdx.x;
    const float* rowbase = qkv + ((size_t)b * S_ + s0) * 4096;
    const float sc = 0.08838834764831845f;

    #pragma unroll
    for (int it = 0; it < 3; ++it) {
        const int c4 = tid * 4 + it * 1024;
        const float* cw = (c4 < 2048) ? cwq + (size_t)c4 * 4
                                      : cwk + (size_t)(c4 - 2048) * 4;
        float4 w0 = *(const float4*)(cw);
        float4 w1 = *(const float4*)(cw + 4);
        float4 w2 = *(const float4*)(cw + 8);
        float4 w3 = *(const float4*)(cw + 12);

        float4 x[7];
        #pragma unroll
        for (int r = 0; r < 7; ++r) {
            int srow = s0 - 3 + r;
            x[r] = (srow >= 0)
                 ? *(const float4*)(rowbase + (ptrdiff_t)(r - 3) * 4096 + c4)
                 : make_float4(0.f, 0.f, 0.f, 0.f);
        }

        #pragma unroll
        for (int o = 0; o < 4; ++o) {
            float4 x0 = x[o + 3];
            float4 acc;
            acc.x = fmaf(w0.x, x0.x, x0.x);
            acc.y = fmaf(w1.x, x0.y, x0.y);
            acc.z = fmaf(w2.x, x0.z, x0.z);
            acc.w = fmaf(w3.x, x0.w, x0.w);
            acc.x = fmaf(w0.y, x[o + 2].x, acc.x);
            acc.y = fmaf(w1.y, x[o + 2].y, acc.y);
            acc.z = fmaf(w2.y, x[o + 2].z, acc.z);
            acc.w = fmaf(w3.y, x[o + 2].w, acc.w);
            acc.x = fmaf(w0.z, x[o + 1].x, acc.x);
            acc.y = fmaf(w1.z, x[o + 1].y, acc.y);
            acc.z = fmaf(w2.z, x[o + 1].z, acc.z);
            acc.w = fmaf(w3.z, x[o + 1].w, acc.w);
            acc.x = fmaf(w0.w, x[o].x, acc.x);
            acc.y = fmaf(w1.w, x[o].y, acc.y);
            acc.z = fmaf(w2.w, x[o].z, acc.z);
            acc.w = fmaf(w3.w, x[o].w, acc.w);
            *(float4*)(sm + o * 3072 + c4) = acc;
        }
    }

    {
        const int c4 = tid * 4 + 3072;
        const float* cw = cwv + (size_t)(c4 - 3072) * 4;
        float4 w0 = *(const float4*)(cw);
        float4 w1 = *(const float4*)(cw + 4);
        float4 w2 = *(const float4*)(cw + 8);
        float4 w3 = *(const float4*)(cw + 12);

        float4 x[7];
        #pragma unroll
        for (int r = 0; r < 7; ++r) {
            int srow = s0 - 3 + r;
            x[r] = (srow >= 0)
                 ? *(const float4*)(rowbase + (ptrdiff_t)(r - 3) * 4096 + c4)
                 : make_float4(0.f, 0.f, 0.f, 0.f);
        }

        float4 vacc[4];
        #pragma unroll
        for (int o = 0; o < 4; ++o) {
            float4 x0 = x[o + 3];
            float4 acc;
            acc.x = fmaf(w0.x, x0.x, x0.x);
            acc.y = fmaf(w1.x, x0.y, x0.y);
            acc.z = fmaf(w2.x, x0.z, x0.z);
            acc.w = fmaf(w3.x, x0.w, x0.w);
            acc.x = fmaf(w0.y, x[o + 2].x, acc.x);
            acc.y = fmaf(w1.y, x[o + 2].y, acc.y);
            acc.z = fmaf(w2.y, x[o + 2].z, acc.z);
            acc.w = fmaf(w3.y, x[o + 2].w, acc.w);
            acc.x = fmaf(w0.z, x[o + 1].x, acc.x);
            acc.y = fmaf(w1.z, x[o + 1].y, acc.y);
            acc.z = fmaf(w2.z, x[o + 1].z, acc.z);
            acc.w = fmaf(w3.z, x[o + 1].w, acc.w);
            acc.x = fmaf(w0.w, x[o].x, acc.x);
            acc.y = fmaf(w1.w, x[o].y, acc.y);
            acc.z = fmaf(w2.w, x[o].z, acc.z);
            acc.w = fmaf(w3.w, x[o].w, acc.w);
            vacc[o] = acc;
        }

        const int vch = c4 - 3072;
        const int kvh = vch >> 7;
        const int d   = vch & 127;
        float* vbase = vto + (((size_t)b * KV_ + kvh) * DH_ + d) * S_ + s0;
        *(float4*)(vbase)           = make_float4(rtf(vacc[0].x), rtf(vacc[1].x), rtf(vacc[2].x), rtf(vacc[3].x));
        *(float4*)(vbase + S_)      = make_float4(rtf(vacc[0].y), rtf(vacc[1].y), rtf(vacc[2].y), rtf(vacc[3].y));
        *(float4*)(vbase + 2 * S_)  = make_float4(rtf(vacc[0].z), rtf(vacc[1].z), rtf(vacc[2].z), rtf(vacc[3].z));
        *(float4*)(vbase + 3 * S_)  = make_float4(rtf(vacc[0].w), rtf(vacc[1].w), rtf(vacc[2].w), rtf(vacc[3].w));
    }
    __syncthreads();

    const int warp = tid >> 5, lane = tid & 31;
    const int j  = lane & 7;
    const int pj = (j < 4) ? 2 * j : 2 * j - 7;
    const int p0 = (lane & ~7) + pj;

    for (int t = warp; t < 96; t += 8) {
        const int o   = t / 24;
        const int h24 = t % 24;
        const int s   = s0 + o;
        const float2 cs0 = rope[(size_t)s * 64 + lane];
        const float2 cs1 = rope[(size_t)s * 64 + lane + 32];
        const bool isq  = h24 < 16;
        const int  base = o * 3072 + (isq ? h24 * 128 : 2048 + (h24 - 16) * 128);
        float v0 = sm[base + lane];
        float v1 = sm[base + lane + 32];
        float v2 = sm[base + lane + 64];
        float v3 = sm[base + lane + 96];
        float ss = v0*v0 + v1*v1 + v2*v2 + v3*v3;
        #pragma unroll
        for (int of = 16; of > 0; of >>= 1) ss += __shfl_xor_sync(0xffffffffu, ss, of);
        float r = rsqrtf(ss * (1.0f / 128.0f) + 1e-6f);
        const float* nw = isq ? qnw : knw;
        float a0 = v0 * r * nw[lane];
        float a1 = v1 * r * nw[lane + 32];
        float a2 = v2 * r * nw[lane + 64];
        float a3 = v3 * r * nw[lane + 96];
        float o_lo0 = a0 * cs0.x - a2 * cs0.y;
        float o_hi0 = a2 * cs0.x + a0 * cs0.y;
        float o_lo1 = a1 * cs1.x - a3 * cs1.y;
        float o_hi1 = a3 * cs1.x + a1 * cs1.y;
        float* dst;
        float f = 1.0f;
        if (isq) { dst = qo + (((size_t)b * H_  + h24)        * S_ + s) * DH_; f = sc; }
        else     { dst = ko + (((size_t)b * KV_ + (h24 - 16)) * S_ + s) * DH_; }
        dst[p0]      = rtf(o_lo0 * f);
        dst[p0 + 32] = rtf(o_lo1 * f);
        dst[p0 + 64] = rtf(o_hi0 * f);
        dst[p0 + 96] = rtf(o_hi1 * f);
    }
}

// ---------------- causal flash attention, tf32 mma.sync ----------------------
// BM=64, BN=32, 128 threads, 2 CTAs/SM: two independent barrier domains per SM
// so one CTA's mma phase hides the other's cp.async wait.  No online max
// (RMSNorm bounds |score| <= 11.31).
#define FB_KS 136
#define FB_VS 40
#define FB_KTILE (32 * FB_KS)          // 4352 floats
#define FB_VTILE (128 * FB_VS)         // 5120 floats
#define FB_BUF  (FB_KTILE + FB_VTILE)  // 9472 floats
#define FB_SMEM (3 * FB_BUF * 4)       // 113664 bytes
#define EPB_S 132

__global__ __launch_bounds__(128, 2) void flash_mma_kernel(
    const float* __restrict__ Q, const float* __restrict__ Kg,
    const float* __restrict__ Vg, float* __restrict__ O)
{
    extern __shared__ float fs[];

    const int qblk = gridDim.x - 1 - blockIdx.x;   // big blocks first
    const int q0   = qblk * 64;
    const int h    = blockIdx.y;
    const int b    = blockIdx.z;
    const int tid  = threadIdx.x;
    const int w    = tid >> 5, lane = tid & 31;
    const int qm   = lane >> 2, qk = lane & 3;
    const int wrow = w * 16;

    const float* Qb = Q  + (((size_t)b * H_  + h)        * S_ + q0 + wrow) * DH_;
    const float* Kb = Kg + (((size_t)b * KV_ + (h >> 1)) * S_) * DH_;
    const float* Vb = Vg + (((size_t)b * KV_ + (h >> 1)) * DH_) * S_;   // V^T

    uint32_t qf[16][4];
    #pragma unroll
    for (int ks = 0; ks < 16; ++ks) {
        float2 q0v = *(const float2*)(Qb + (size_t)qm * DH_ + ks * 8 + 2 * qk);
        float2 q1v = *(const float2*)(Qb + (size_t)(qm + 8) * DH_ + ks * 8 + 2 * qk);
        qf[ks][0] = __float_as_uint(q0v.x);
        qf[ks][1] = __float_as_uint(q1v.x);
        qf[ks][2] = __float_as_uint(q0v.y);
        qf[ks][3] = __float_as_uint(q1v.y);
    }

    float o[16][4];
    #pragma unroll
    for (int nt = 0; nt < 16; ++nt)
        o[nt][0] = o[nt][1] = o[nt][2] = o[nt][3] = 0.f;
    float l0 = 0.f, l1 = 0.f;

    const int nb = 2 * (qblk + 1);        // tiles of 32 KV rows
    const uint32_t fs_u = smem_u32(fs);

    auto prefetch = [&](int jb, int buf) {
        const int j0 = jb * 32;
        const uint32_t kbuf = fs_u + (uint32_t)buf * FB_BUF * 4;
        const uint32_t vbuf = kbuf + FB_KTILE * 4;
        #pragma unroll
        for (int i = 0; i < 8; ++i) {
            int idx = tid + i * 128;
            {   // K: 32 rows x 128 floats
                int row = idx >> 5, c4 = idx & 31;
                cp_async16(kbuf + (uint32_t)(row * FB_KS + c4 * 4) * 4,
                           Kb + (size_t)(j0 + row) * DH_ + c4 * 4);
            }
            {   // V^T: 128 rows x 32 floats
                int row = idx >> 3, c4 = idx & 7;
                cp_async16(vbuf + (uint32_t)(row * FB_VS + c4 * 4) * 4,
                           Vb + (size_t)row * S_ + j0 + c4 * 4);
            }
        }
        cp_commit();
    };

    prefetch(0, 0);
    if (nb > 1) prefetch(1, 1);

    for (int jb = 0; jb < nb; ++jb) {
        const int buf = jb % 3;
        const int j0  = jb * 32;

        if (jb + 1 < nb) cp_wait<1>();
        else             cp_wait<0>();
        __syncthreads();

        if (jb + 2 < nb) prefetch(jb + 2, (jb + 2) % 3);

        const float* Kt = fs + (size_t)buf * FB_BUF;
        const float* Vt = Kt + FB_KTILE;

        // ---- S = Q K^T (4 n-tiles of 8 KV rows) ----
        float sv[4][4];
        #pragma unroll
        for (int nt = 0; nt < 4; ++nt) {
            sv[nt][0] = sv[nt][1] = sv[nt][2] = sv[nt][3] = 0.f;
            const float* kp = Kt + (nt * 8 + qm) * FB_KS + 2 * qk;
            #pragma unroll
            for (int ks = 0; ks < 16; ++ks) {
                float2 kv = *(const float2*)(kp + ks * 8);
                uint32_t bfr[2];
                bfr[0] = __float_as_uint(kv.x);
                bfr[1] = __float_as_uint(kv.y);
                mma_tf32(sv[nt], qf[ks], bfr);
            }
        }

        // ---- causal mask (last two tiles) ----
        if (jb >= nb - 2) {
            const int r0 = q0 + wrow + qm, r1 = r0 + 8;
            #pragma unroll
            for (int nt = 0; nt < 4; ++nt) {
                const int c0 = j0 + nt * 8 + 2 * qk;
                if (c0     > r0) sv[nt][0] = -1e30f;
                if (c0 + 1 > r0) sv[nt][1] = -1e30f;
                if (c0     > r1) sv[nt][2] = -1e30f;
                if (c0 + 1 > r1) sv[nt][3] = -1e30f;
            }
        }

        // ---- softmax without running max ----
        uint32_t aP[4][4];
        float rs0 = 0.f, rs1 = 0.f;
        #pragma unroll
        for (int nt = 0; nt < 4; ++nt) {
            float p00 = __expf(sv[nt][0]);
            float p01 = __expf(sv[nt][1]);
            float p10 = __expf(sv[nt][2]);
            float p11 = __expf(sv[nt][3]);
            rs0 += p00 + p01;
            rs1 += p10 + p11;
            aP[nt][0] = f2tf32(p00);
            aP[nt][1] = f2tf32(p10);
            aP[nt][2] = f2tf32(p01);
            aP[nt][3] = f2tf32(p11);
        }
        l0 += rs0;
        l1 += rs1;

        // ---- O += P V ----
        #pragma unroll
        for (int nt = 0; nt < 16; ++nt) {
            const float* vp = Vt + (nt * 8 + qm) * FB_VS + 2 * qk;
            #pragma unroll
            for (int ks = 0; ks < 4; ++ks) {
                float2 vv = *(const float2*)(vp + ks * 8);
                uint32_t bfr[2];
                bfr[0] = __float_as_uint(vv.x);
                bfr[1] = __float_as_uint(vv.y);
                mma_tf32(o[nt], aP[ks], bfr);
            }
        }
    }

    // ---- l reduction ----
    l0 += __shfl_xor_sync(0xffffffffu, l0, 1);
    l0 += __shfl_xor_sync(0xffffffffu, l0, 2);
    l1 += __shfl_xor_sync(0xffffffffu, l1, 1);
    l1 += __shfl_xor_sync(0xffffffffu, l1, 2);
    const float il0 = 1.f / l0, il1 = 1.f / l1;

    // ---- epilogue: stage via smem, coalesced float4 writes ----
    __syncthreads();
    const int pos0 = (qk < 2) ? 4 * qk : 4 * qk - 7;
    const int pos1 = pos0 + 2;
    float* st0 = fs + (wrow + qm) * EPB_S;
    float* st1 = st0 + 8 * EPB_S;
    #pragma unroll
    for (int nt = 0; nt < 16; ++nt) {
        st0[nt * 8 + pos0] = o[nt][0] * il0;
        st0[nt * 8 + pos1] = o[nt][1] * il0;
        st1[nt * 8 + pos0] = o[nt][2] * il1;
        st1[nt * 8 + pos1] = o[nt][3] * il1;
    }
    __syncthreads();
    #pragma unroll
    for (int i = 0; i < 16; ++i) {
        int idx = tid + i * 128;
        int r = idx >> 5, c4 = (idx & 31) * 4;
        const float* src = fs + r * EPB_S + c4;
        float4 v = make_float4(rtf(src[0]), rtf(src[1]), rtf(src[2]), rtf(src[3]));
        *(float4*)(O + ((size_t)b * S_ + q0 + r) * D_ + h * DH_ + c4) = v;
    }
}

// ---------------- launch ----------------
extern "C" void kernel_launch(void* const* d_in, const int* in_sizes, int n_in,
                              void* d_out, int out_size)
{
    const float* hidden = (const float*)d_in[0];
    const float* Wq     = (const float*)d_in[1];
    const float* Wk     = (const float*)d_in[2];
    const float* Wv     = (const float*)d_in[3];
    const float* Wo     = (const float*)d_in[4];
    const float* cwq    = (const float*)d_in[5];
    const float* cwk    = (const float*)d_in[6];
    const float* cwv    = (const float*)d_in[7];
    const float* qnw    = (const float*)d_in[8];
    const float* knw    = (const float*)d_in[9];
    float* out = (float*)d_out;

    float *qkv, *q, *k, *vt, *attn, *hid, *wq, *wk, *wv, *wo;
    float2* rope;
    cudaGetSymbolAddress((void**)&qkv,  g_qkv);
    cudaGetSymbolAddress((void**)&q,    g_q);
    cudaGetSymbolAddress((void**)&k,    g_k);
    cudaGetSymbolAddress((void**)&vt,   g_vt);
    cudaGetSymbolAddress((void**)&attn, g_attn);
    cudaGetSymbolAddress((void**)&rope, g_rope);
    cudaGetSymbolAddress((void**)&hid,  g_hid);
    cudaGetSymbolAddress((void**)&wq,   g_wq);
    cudaGetSymbolAddress((void**)&wk,   g_wk);
    cudaGetSymbolAddress((void**)&wv,   g_wv);
    cudaGetSymbolAddress((void**)&wo,   g_wo);

    const int nh = B_ * S_ * D_ / 8;
    const int nq = D_ * D_ / 8;
    const int nk = 1024 * D_ / 8;
    permute_round_all<<<dim3((nh + 255) / 256, 6), 256>>>(
        hidden, hid, nh,
        Wq, wq, nq,
        Wk, wk, nk,
        Wv, wv, nk,
        Wo, wo, nq,
        rope);

    cudaFuncSetAttribute(gemm_mma, cudaFuncAttributeMaxDynamicSharedMemorySize, GEMM_SMEM);

    gemm_mma<<<dim3(4096 / TN, (B_ * S_) / TM), 128, GEMM_SMEM>>>(
        hid, wq, wk, wv, qkv, 2048, 4096, 2048, 3072);

    cudaFuncSetAttribute(postproc_kernel, cudaFuncAttributeMaxDynamicSharedMemorySize, PP_SMEM);
    postproc_kernel<<<dim3(S_ / 4, B_), 256, PP_SMEM>>>(
        qkv, cwq, cwk, cwv, qnw, knw, rope, q, k, vt);

    cudaFuncSetAttribute(flash_mma_kernel, cudaFuncAttributeMaxDynamicSharedMemorySize, FB_SMEM);
    flash_mma_kernel<<<dim3(S_ / 64, H_, B_), 128, FB_SMEM>>>(q, k, vt, attn);

    gemm_mma<<<dim3(D_ / TN, (B_ * S_) / TM), 128, GEMM_SMEM>>>(
        attn, wo, wo, wo, out, 2048, 2048, 1 << 30, 1 << 30);
}